// round 2
// baseline (speedup 1.0000x reference)
#include <cuda_runtime.h>
#include <math.h>
#include <stdint.h>

#define BB 4
#define SQ 2048
#define EE 1024
#define HH 16
#define DH 64
#define ROWS 16
#define KT 64

#define GM (BB*SQ)     // 8192
#define GN (3*EE)      // 3072
#define GK (EE)        // 1024

// Scratch for qkv projection result: [B, S, 3E] = 100.7 MB
__device__ float g_qkv[(size_t)BB * SQ * 3 * EE];

// ---------------------------------------------------------------------------
// QKV GEMM: C[M,N] = A[M,K] @ W[N,K]^T   (A = x flattened, W = W_qkv)
// 64x64 tile, 256 threads, 4x4 per thread, K-tile 16.
// ---------------------------------------------------------------------------
__global__ __launch_bounds__(256) void qkv_gemm_kernel(
    const float* __restrict__ A, const float* __restrict__ W, float* __restrict__ C)
{
    __shared__ float As[16][68];   // [k][m], padded
    __shared__ float Bs[16][68];   // [k][n], padded

    const int tid = threadIdx.x;
    const int tx = tid & 15;       // n-group
    const int ty = tid >> 4;       // m-group
    const int m0 = blockIdx.y * 64;
    const int n0 = blockIdx.x * 64;

    float acc[4][4] = {};

    const int lc = tid & 15;       // k within tile
    const int lr = tid >> 4;       // row base (16 rows per pass)

    for (int k0 = 0; k0 < GK; k0 += 16) {
        #pragma unroll
        for (int it = 0; it < 4; it++) {
            int r = lr + it * 16;
            As[lc][r] = A[(size_t)(m0 + r) * GK + k0 + lc];
            Bs[lc][r] = W[(size_t)(n0 + r) * GK + k0 + lc];
        }
        __syncthreads();
        #pragma unroll
        for (int kk = 0; kk < 16; kk++) {
            float4 a4 = *(const float4*)&As[kk][ty * 4];
            float4 b4 = *(const float4*)&Bs[kk][tx * 4];
            float a[4] = {a4.x, a4.y, a4.z, a4.w};
            float b[4] = {b4.x, b4.y, b4.z, b4.w};
            #pragma unroll
            for (int i = 0; i < 4; i++)
                #pragma unroll
                for (int j = 0; j < 4; j++)
                    acc[i][j] += a[i] * b[j];
        }
        __syncthreads();
    }

    #pragma unroll
    for (int i = 0; i < 4; i++)
        #pragma unroll
        for (int j = 0; j < 4; j++)
            C[(size_t)(m0 + ty * 4 + i) * GN + n0 + tx * 4 + j] = acc[i][j];
}

// ---------------------------------------------------------------------------
// Fused causal ALiBi attention.
// One CTA per (b, h, 16-query-row tile). Score rows kept entirely in smem.
// smem: sc[16][2048] fp32 (128KB) + kv tile [64][65] (16.6KB) + q tile (4KB)
// ---------------------------------------------------------------------------
__global__ __launch_bounds__(256, 1) void attn_kernel(
    const float* __restrict__ qkv, float* __restrict__ out,
    float* __restrict__ attn, int write_attn)
{
    extern __shared__ float smem[];
    float* sc = smem;                        // ROWS * SQ
    float* kq = sc + ROWS * SQ;              // KT * (DH+1)
    float* qs = kq + KT * (DH + 1);          // ROWS * DH

    const int i0 = blockIdx.x * ROWS;
    const int h  = blockIdx.y;
    const int b  = blockIdx.z;
    const int tid = threadIdx.x;
    const int lane = tid & 31;
    const int w = tid >> 5;                  // warp id 0..7

    const float slope = exp2f(-0.5f * (float)(h + 1));   // 1 / (2^8)^((h+1)/16)
    const float inv_scale = 1.0f / 32.0f;                // 1/sqrt(E)

    // --- load Q rows (q chunk = middle third of qkv) ---
    for (int idx = tid; idx < ROWS * DH; idx += 256) {
        int r = idx / DH, d = idx % DH;
        qs[r * DH + d] = qkv[(size_t)(b * SQ + i0 + r) * (3 * EE) + EE + h * DH + d];
    }
    __syncthreads();

    const int imax = i0 + ROWS - 1;
    const int jend = ((imax / KT) + 1) * KT;   // causal extent, multiple of 64

    const int r0 = w, r1 = w + 8;
    const int gi0 = i0 + r0, gi1 = i0 + r1;

    // --- scores: S = QK^T/scale + alibi, masked -> -inf ---
    for (int jt = 0; jt < jend; jt += KT) {
        for (int idx = tid; idx < KT * DH; idx += 256) {
            int jj = idx / DH, d = idx % DH;
            kq[jj * (DH + 1) + d] = qkv[(size_t)(b * SQ + jt + jj) * (3 * EE) + h * DH + d];
        }
        __syncthreads();

        float s00 = 0.f, s01 = 0.f, s10 = 0.f, s11 = 0.f;
        const float* q0 = &qs[r0 * DH];
        const float* q1 = &qs[r1 * DH];
        const float* k0 = &kq[lane * (DH + 1)];
        const float* k1 = &kq[(lane + 32) * (DH + 1)];
        #pragma unroll 16
        for (int d = 0; d < DH; d++) {
            float a0 = q0[d], a1 = q1[d];
            float b0 = k0[d], b1 = k1[d];
            s00 += a0 * b0; s01 += a0 * b1;
            s10 += a1 * b0; s11 += a1 * b1;
        }
        int j0 = jt + lane, j1 = jt + lane + 32;
        sc[r0 * SQ + j0] = (j0 <= gi0) ? fmaf(slope, (float)(j0 - gi0), s00 * inv_scale) : -INFINITY;
        sc[r0 * SQ + j1] = (j1 <= gi0) ? fmaf(slope, (float)(j1 - gi0), s01 * inv_scale) : -INFINITY;
        sc[r1 * SQ + j0] = (j0 <= gi1) ? fmaf(slope, (float)(j0 - gi1), s10 * inv_scale) : -INFINITY;
        sc[r1 * SQ + j1] = (j1 <= gi1) ? fmaf(slope, (float)(j1 - gi1), s11 * inv_scale) : -INFINITY;
        __syncthreads();
    }

    // --- softmax: warp w owns rows w and w+8 ---
    #pragma unroll
    for (int rr = 0; rr < 2; rr++) {
        int r = w + rr * 8;
        float* row = &sc[r * SQ];
        float mx = -INFINITY;
        for (int j = lane; j < jend; j += 32) mx = fmaxf(mx, row[j]);
        #pragma unroll
        for (int o = 16; o; o >>= 1) mx = fmaxf(mx, __shfl_xor_sync(0xffffffffu, mx, o));
        float sum = 0.f;
        for (int j = lane; j < jend; j += 32) {
            float e = expf(row[j] - mx);     // exp(-inf - mx) = 0
            row[j] = e;
            sum += e;
        }
        #pragma unroll
        for (int o = 16; o; o >>= 1) sum += __shfl_xor_sync(0xffffffffu, sum, o);
        float inv = 1.0f / sum;
        for (int j = lane; j < jend; j += 32) row[j] *= inv;
    }
    __syncthreads();

    // --- write attn rows (coalesced), zeros past causal extent ---
    if (write_attn) {
        for (int idx = tid; idx < ROWS * SQ; idx += 256) {
            int r = idx / SQ, j = idx % SQ;
            float v = (j < jend) ? sc[r * SQ + j] : 0.0f;
            attn[((size_t)((b * HH + h) * SQ + i0 + r)) * SQ + j] = v;
        }
    }

    // --- PV: out = attn @ V ---
    float a00 = 0.f, a01 = 0.f, a10 = 0.f, a11 = 0.f;
    for (int jt = 0; jt < jend; jt += KT) {
        __syncthreads();
        for (int idx = tid; idx < KT * DH; idx += 256) {
            int jj = idx / DH, d = idx % DH;
            kq[jj * (DH + 1) + d] = qkv[(size_t)(b * SQ + jt + jj) * (3 * EE) + 2 * EE + h * DH + d];
        }
        __syncthreads();
        const float* p0 = &sc[r0 * SQ + jt];
        const float* p1 = &sc[r1 * SQ + jt];
        #pragma unroll 8
        for (int jj = 0; jj < KT; jj++) {
            float pv0 = p0[jj], pv1 = p1[jj];
            float v0 = kq[jj * (DH + 1) + lane];
            float v1 = kq[jj * (DH + 1) + lane + 32];
            a00 += pv0 * v0; a01 += pv0 * v1;
            a10 += pv1 * v0; a11 += pv1 * v1;
        }
    }

    out[(size_t)(b * SQ + gi0) * EE + h * DH + lane]      = a00;
    out[(size_t)(b * SQ + gi0) * EE + h * DH + lane + 32] = a01;
    out[(size_t)(b * SQ + gi1) * EE + h * DH + lane]      = a10;
    out[(size_t)(b * SQ + gi1) * EE + h * DH + lane + 32] = a11;
}

// ---------------------------------------------------------------------------
extern "C" void kernel_launch(void* const* d_in, const int* in_sizes, int n_in,
                              void* d_out, int out_size)
{
    const float* x = (const float*)d_in[0];
    const float* W = (const float*)d_in[1];
    float* out = (float*)d_out;

    const long out_elems  = (long)BB * SQ * EE;               // 8,388,608
    const long attn_elems = (long)BB * HH * SQ * SQ;          // 268,435,456
    int write_attn = ((long)out_size >= out_elems + attn_elems) ? 1 : 0;
    float* attn = write_attn ? (out + out_elems) : nullptr;

    float* qkv;
    cudaGetSymbolAddress((void**)&qkv, g_qkv);

    // QKV projection
    {
        dim3 grid(GN / 64, GM / 64);
        qkv_gemm_kernel<<<grid, 256>>>(x, W, qkv);
    }

    // Fused attention
    {
        int smem_bytes = (ROWS * SQ + KT * (DH + 1) + ROWS * DH) * (int)sizeof(float);
        cudaFuncSetAttribute(attn_kernel, cudaFuncAttributeMaxDynamicSharedMemorySize, smem_bytes);
        dim3 grid(SQ / ROWS, HH, BB);
        attn_kernel<<<grid, 256, smem_bytes>>>(qkv, out, attn, write_attn);
    }
}

// round 4
// speedup vs baseline: 1.1183x; 1.1183x over previous
#include <cuda_runtime.h>
#include <math.h>
#include <stdint.h>

#define BB 4
#define SQ 2048
#define EE 1024
#define HH 16
#define DH 64
#define ROWS 16
#define KT 64

#define GM (BB*SQ)     // 8192
#define GN (3*EE)      // 3072
#define GK (EE)        // 1024

// Scratch for qkv projection result: [B, S, 3E] = 100.7 MB
__device__ float g_qkv[(size_t)BB * SQ * 3 * EE];

// ---------------------------------------------------------------------------
// QKV GEMM: C[M,N] = A[M,K] @ W[N,K]^T
// 128x128 tile, 256 threads, 8x8 per thread, K-slab 8, double-buffered smem.
// ---------------------------------------------------------------------------
__global__ __launch_bounds__(256, 2) void qkv_gemm_kernel(
    const float* __restrict__ A, const float* __restrict__ W, float* __restrict__ C)
{
    __shared__ float As[2][8][132];
    __shared__ float Bs[2][8][132];

    const int tid = threadIdx.x;
    const int tx = tid & 15;
    const int ty = tid >> 4;
    const int m0 = blockIdx.y * 128;
    const int n0 = blockIdx.x * 128;

    const int lr = tid >> 1;          // 0..127
    const int lk = (tid & 1) * 4;     // 0 or 4

    const float* Aptr = A + (size_t)(m0 + lr) * GK + lk;
    const float* Wptr = W + (size_t)(n0 + lr) * GK + lk;

    float acc[8][8] = {};

    // prologue: load slab 0
    {
        float4 a = *(const float4*)Aptr;
        float4 b = *(const float4*)Wptr;
        As[0][lk + 0][lr] = a.x; As[0][lk + 1][lr] = a.y;
        As[0][lk + 2][lr] = a.z; As[0][lk + 3][lr] = a.w;
        Bs[0][lk + 0][lr] = b.x; Bs[0][lk + 1][lr] = b.y;
        Bs[0][lk + 2][lr] = b.z; Bs[0][lk + 3][lr] = b.w;
    }
    __syncthreads();

    const int NS = GK / 8;   // 128 slabs
    for (int s = 0; s < NS; s++) {
        const int cur = s & 1;
        float4 a_nx, b_nx;
        if (s + 1 < NS) {
            a_nx = *(const float4*)(Aptr + (s + 1) * 8);
            b_nx = *(const float4*)(Wptr + (s + 1) * 8);
        }

        #pragma unroll
        for (int kk = 0; kk < 8; kk++) {
            float4 a0 = *(const float4*)&As[cur][kk][ty * 4];
            float4 a1 = *(const float4*)&As[cur][kk][ty * 4 + 64];
            float4 b0 = *(const float4*)&Bs[cur][kk][tx * 4];
            float4 b1 = *(const float4*)&Bs[cur][kk][tx * 4 + 64];
            float ar[8] = {a0.x, a0.y, a0.z, a0.w, a1.x, a1.y, a1.z, a1.w};
            float br[8] = {b0.x, b0.y, b0.z, b0.w, b1.x, b1.y, b1.z, b1.w};
            #pragma unroll
            for (int i = 0; i < 8; i++)
                #pragma unroll
                for (int j = 0; j < 8; j++)
                    acc[i][j] += ar[i] * br[j];
        }

        if (s + 1 < NS) {
            const int nxt = cur ^ 1;
            As[nxt][lk + 0][lr] = a_nx.x; As[nxt][lk + 1][lr] = a_nx.y;
            As[nxt][lk + 2][lr] = a_nx.z; As[nxt][lk + 3][lr] = a_nx.w;
            Bs[nxt][lk + 0][lr] = b_nx.x; Bs[nxt][lk + 1][lr] = b_nx.y;
            Bs[nxt][lk + 2][lr] = b_nx.z; Bs[nxt][lk + 3][lr] = b_nx.w;
        }
        __syncthreads();
    }

    #pragma unroll
    for (int i = 0; i < 8; i++) {
        int m = m0 + ((i < 4) ? (ty * 4 + i) : (64 + ty * 4 + i - 4));
        float4 c0 = make_float4(acc[i][0], acc[i][1], acc[i][2], acc[i][3]);
        float4 c1 = make_float4(acc[i][4], acc[i][5], acc[i][6], acc[i][7]);
        *(float4*)&C[(size_t)m * GN + n0 + tx * 4]      = c0;
        *(float4*)&C[(size_t)m * GN + n0 + 64 + tx * 4] = c1;
    }
}

// ---------------------------------------------------------------------------
// Fused causal ALiBi attention.
// One CTA per (b, h, 16-row query tile). 512 threads = 16 warps, 1 row/warp.
// smem: sc[16][2048] (128KB) + kv[64][68] (17.4KB) + qs[16][68] (4.3KB)
// ---------------------------------------------------------------------------
__global__ __launch_bounds__(512, 1) void attn_kernel(
    const float* __restrict__ qkv, float* __restrict__ out,
    float* __restrict__ attn, int write_attn)
{
    extern __shared__ float smem[];
    float* sc = smem;                        // ROWS * SQ
    float* kq = sc + ROWS * SQ;              // KT * 68
    float* qs = kq + KT * 68;                // ROWS * 68

    const int i0 = blockIdx.x * ROWS;
    const int h  = blockIdx.y;
    const int b  = blockIdx.z;
    const int tid = threadIdx.x;
    const int lane = tid & 31;
    const int w = tid >> 5;                  // warp id 0..15 = row
    const int gi = i0 + w;

    const float slope = exp2f(-0.5f * (float)(h + 1));   // 1 / (2^8)^((h+1)/16)
    const float inv_scale = 1.0f / 32.0f;                // 1/sqrt(E)

    // --- load Q (16 x 64), q chunk = middle third ---
    if (tid < 256) {
        int r = tid >> 4, dc = (tid & 15) * 4;
        float4 v = *(const float4*)&qkv[(size_t)(b * SQ + i0 + r) * (3 * EE) + EE + h * DH + dc];
        *(float4*)&qs[r * 68 + dc] = v;
    }
    __syncthreads();

    const int jend = ((i0 + ROWS - 1) / KT + 1) * KT;   // causal extent

    // --- scores: S = QK^T/scale + alibi, masked -> -inf ---
    for (int jt = 0; jt < jend; jt += KT) {
        for (int idx = tid; idx < KT * 16; idx += 512) {
            int jj = idx >> 4, dc = (idx & 15) * 4;
            float4 v = *(const float4*)&qkv[(size_t)(b * SQ + jt + jj) * (3 * EE) + h * DH + dc];
            *(float4*)&kq[jj * 68 + dc] = v;
        }
        __syncthreads();

        float s0 = 0.f, s1 = 0.f;
        const float* qr  = qs + w * 68;
        const float* k0p = kq + lane * 68;
        const float* k1p = kq + (lane + 32) * 68;
        #pragma unroll
        for (int d = 0; d < DH; d += 4) {
            float4 qv = *(const float4*)(qr + d);
            float4 k0 = *(const float4*)(k0p + d);
            float4 k1 = *(const float4*)(k1p + d);
            s0 += qv.x * k0.x + qv.y * k0.y + qv.z * k0.z + qv.w * k0.w;
            s1 += qv.x * k1.x + qv.y * k1.y + qv.z * k1.z + qv.w * k1.w;
        }
        int j0 = jt + lane, j1 = j0 + 32;
        sc[w * SQ + j0] = (j0 <= gi) ? fmaf(slope, (float)(j0 - gi), s0 * inv_scale) : -INFINITY;
        sc[w * SQ + j1] = (j1 <= gi) ? fmaf(slope, (float)(j1 - gi), s1 * inv_scale) : -INFINITY;
        __syncthreads();
    }

    // --- softmax: warp w owns row w; keep probs UNNORMALIZED, fold 1/sum later ---
    float* row = sc + w * SQ;
    float mx = -INFINITY;
    for (int j = lane; j < jend; j += 32) mx = fmaxf(mx, row[j]);
    #pragma unroll
    for (int o = 16; o; o >>= 1) mx = fmaxf(mx, __shfl_xor_sync(0xffffffffu, mx, o));
    float sum = 0.f;
    for (int j = lane; j < jend; j += 32) {
        float e = __expf(row[j] - mx);       // exp(-inf - mx) = 0
        row[j] = e;
        sum += e;
    }
    #pragma unroll
    for (int o = 16; o; o >>= 1) sum += __shfl_xor_sync(0xffffffffu, sum, o);
    const float inv = 1.0f / sum;

    // --- write attn row (coalesced), normalized, zeros past causal extent ---
    if (write_attn) {
        float* arow = attn + ((size_t)((b * HH + h) * SQ + gi)) * SQ;
        for (int j = lane; j < SQ; j += 32)
            arow[j] = (j < jend) ? row[j] * inv : 0.0f;
    }

    // --- PV with transposed V tile: vq[d][jj] = V[jj][d] ---
    float a0 = 0.f, a1 = 0.f;
    for (int jt = 0; jt < jend; jt += KT) {
        __syncthreads();
        for (int idx = tid; idx < KT * DH; idx += 512) {
            int jj = idx >> 6, d = idx & 63;
            kq[d * 68 + jj] = qkv[(size_t)(b * SQ + jt + jj) * (3 * EE) + 2 * EE + h * DH + d];
        }
        __syncthreads();
        const float* pr  = sc + w * SQ + jt;
        const float* v0p = kq + lane * 68;
        const float* v1p = kq + (lane + 32) * 68;
        #pragma unroll
        for (int jj = 0; jj < KT; jj += 4) {
            float4 p  = *(const float4*)(pr + jj);
            float4 v0 = *(const float4*)(v0p + jj);
            float4 v1 = *(const float4*)(v1p + jj);
            a0 += p.x * v0.x + p.y * v0.y + p.z * v0.z + p.w * v0.w;
            a1 += p.x * v1.x + p.y * v1.y + p.z * v1.z + p.w * v1.w;
        }
    }

    out[(size_t)(b * SQ + gi) * EE + h * DH + lane]      = a0 * inv;
    out[(size_t)(b * SQ + gi) * EE + h * DH + lane + 32] = a1 * inv;
}

// ---------------------------------------------------------------------------
extern "C" void kernel_launch(void* const* d_in, const int* in_sizes, int n_in,
                              void* d_out, int out_size)
{
    const float* x = (const float*)d_in[0];
    const float* W = (const float*)d_in[1];
    float* out = (float*)d_out;

    const long out_elems  = (long)BB * SQ * EE;               // 8,388,608
    const long attn_elems = (long)BB * HH * SQ * SQ;          // 268,435,456
    int write_attn = ((long)out_size >= out_elems + attn_elems) ? 1 : 0;
    float* attn = write_attn ? (out + out_elems) : nullptr;

    float* qkv;
    cudaGetSymbolAddress((void**)&qkv, g_qkv);

    // QKV projection
    {
        dim3 grid(GN / 128, GM / 128);
        qkv_gemm_kernel<<<grid, 256>>>(x, W, qkv);
    }

    // Fused attention
    {
        int smem_bytes = (ROWS * SQ + KT * 68 + ROWS * 68) * (int)sizeof(float);
        cudaFuncSetAttribute(attn_kernel, cudaFuncAttributeMaxDynamicSharedMemorySize, smem_bytes);
        dim3 grid(SQ / ROWS, HH, BB);
        attn_kernel<<<grid, 512, smem_bytes>>>(qkv, out, attn, write_attn);
    }
}

// round 6
// speedup vs baseline: 1.5701x; 1.4040x over previous
#include <cuda_runtime.h>
#include <math.h>
#include <stdint.h>

#define BB 4
#define SQ 2048
#define EE 1024
#define HH 16
#define DH 64
#define ROWS 16
#define KT 256

#define GM (BB*SQ)     // 8192
#define GN (3*EE)      // 3072
#define GK (EE)        // 1024

// Scratch for qkv projection result: [B, S, 3E] = 100.7 MB
__device__ float g_qkv[(size_t)BB * SQ * 3 * EE];

// ---------------------------------------------------------------------------
// QKV GEMM: C[M,N] = A[M,K] @ W[N,K]^T
// 128x128 tile, 256 threads, 8x8 per thread, K-slab 8, double-buffered smem.
// ---------------------------------------------------------------------------
__global__ __launch_bounds__(256, 2) void qkv_gemm_kernel(
    const float* __restrict__ A, const float* __restrict__ W, float* __restrict__ C)
{
    __shared__ float As[2][8][132];
    __shared__ float Bs[2][8][132];

    const int tid = threadIdx.x;
    const int tx = tid & 15;
    const int ty = tid >> 4;
    const int m0 = blockIdx.y * 128;
    const int n0 = blockIdx.x * 128;

    const int lr = tid >> 1;          // 0..127
    const int lk = (tid & 1) * 4;     // 0 or 4

    const float* Aptr = A + (size_t)(m0 + lr) * GK + lk;
    const float* Wptr = W + (size_t)(n0 + lr) * GK + lk;

    float acc[8][8] = {};

    {
        float4 a = *(const float4*)Aptr;
        float4 b = *(const float4*)Wptr;
        As[0][lk + 0][lr] = a.x; As[0][lk + 1][lr] = a.y;
        As[0][lk + 2][lr] = a.z; As[0][lk + 3][lr] = a.w;
        Bs[0][lk + 0][lr] = b.x; Bs[0][lk + 1][lr] = b.y;
        Bs[0][lk + 2][lr] = b.z; Bs[0][lk + 3][lr] = b.w;
    }
    __syncthreads();

    const int NS = GK / 8;   // 128 slabs
    for (int s = 0; s < NS; s++) {
        const int cur = s & 1;
        float4 a_nx, b_nx;
        if (s + 1 < NS) {
            a_nx = *(const float4*)(Aptr + (s + 1) * 8);
            b_nx = *(const float4*)(Wptr + (s + 1) * 8);
        }

        #pragma unroll
        for (int kk = 0; kk < 8; kk++) {
            float4 a0 = *(const float4*)&As[cur][kk][ty * 4];
            float4 a1 = *(const float4*)&As[cur][kk][ty * 4 + 64];
            float4 b0 = *(const float4*)&Bs[cur][kk][tx * 4];
            float4 b1 = *(const float4*)&Bs[cur][kk][tx * 4 + 64];
            float ar[8] = {a0.x, a0.y, a0.z, a0.w, a1.x, a1.y, a1.z, a1.w};
            float br[8] = {b0.x, b0.y, b0.z, b0.w, b1.x, b1.y, b1.z, b1.w};
            #pragma unroll
            for (int i = 0; i < 8; i++)
                #pragma unroll
                for (int j = 0; j < 8; j++)
                    acc[i][j] += ar[i] * br[j];
        }

        if (s + 1 < NS) {
            const int nxt = cur ^ 1;
            As[nxt][lk + 0][lr] = a_nx.x; As[nxt][lk + 1][lr] = a_nx.y;
            As[nxt][lk + 2][lr] = a_nx.z; As[nxt][lk + 3][lr] = a_nx.w;
            Bs[nxt][lk + 0][lr] = b_nx.x; Bs[nxt][lk + 1][lr] = b_nx.y;
            Bs[nxt][lk + 2][lr] = b_nx.z; Bs[nxt][lk + 3][lr] = b_nx.w;
        }
        __syncthreads();
    }

    #pragma unroll
    for (int i = 0; i < 8; i++) {
        int m = m0 + ((i < 4) ? (ty * 4 + i) : (64 + ty * 4 + i - 4));
        float4 c0 = make_float4(acc[i][0], acc[i][1], acc[i][2], acc[i][3]);
        float4 c1 = make_float4(acc[i][4], acc[i][5], acc[i][6], acc[i][7]);
        *(float4*)&C[(size_t)m * GN + n0 + tx * 4]      = c0;
        *(float4*)&C[(size_t)m * GN + n0 + 64 + tx * 4] = c1;
    }
}

// ---------------------------------------------------------------------------
// Fused causal ALiBi attention, register-blocked 4 rows x 2 keys per warp.
// One CTA per (b, h, 16-row query tile). 512 threads = 16 warps:
//   warp = 4 row-groups x 4 key-slabs (KT=256 keys per tile pass).
// smem: sc[16][2048] fp32 (128KB) + kq[256*68|64*260] (68KB) + qs + sinv
// ---------------------------------------------------------------------------
__global__ __launch_bounds__(512, 1) void attn_kernel(
    const float* __restrict__ qkv, float* __restrict__ out,
    float* __restrict__ attn, int write_attn)
{
    extern __shared__ float smem[];
    float* sc  = smem;                     // 16 * 2048
    float* kq  = sc + ROWS * SQ;           // 17408 floats (K tile / V^T tile / reduce)
    float* qs  = kq + 17408;               // 16 * 68
    float* sinv = qs + ROWS * 68;          // 16

    const int i0 = (gridDim.x - 1 - blockIdx.x) * ROWS;   // longest tiles first
    const int h  = blockIdx.y;
    const int b  = blockIdx.z;
    const int tid = threadIdx.x;
    const int lane = tid & 31;
    const int w = tid >> 5;                // warp 0..15
    const int rg = w & 3;                  // row group: rows rg*4 .. rg*4+3
    const int ks = w >> 2;                 // key slab: keys ks*64 + lane, +32

    const float slope = exp2f(-0.5f * (float)(h + 1));   // 1/(2^8)^((h+1)/16)
    const float inv_scale = 1.0f / 32.0f;                // 1/sqrt(E)

    // --- load Q (16 x 64), q chunk = middle third of qkv ---
    if (tid < 256) {
        int r = tid >> 4, dc = (tid & 15) * 4;
        float4 v = *(const float4*)&qkv[(size_t)(b * SQ + i0 + r) * (3 * EE) + EE + h * DH + dc];
        *(float4*)&qs[r * 68 + dc] = v;
    }
    __syncthreads();

    const int jend = ((i0 + ROWS - 1) / 64 + 1) * 64;   // causal extent, mult of 64

    // ======================= scores =======================
    for (int jt = 0; jt < jend; jt += KT) {
        const int ktile = min(KT, jend - jt);           // multiple of 64
        for (int idx = tid; idx < ktile * 16; idx += 512) {
            int jj = idx >> 4, dc = (idx & 15) * 4;
            float4 v = *(const float4*)&qkv[(size_t)(b * SQ + jt + jj) * (3 * EE) + h * DH + dc];
            *(float4*)&kq[jj * 68 + dc] = v;
        }
        __syncthreads();

        if (ks * 64 < ktile) {
            float acc[4][2] = {};
            const float* k0p = kq + (ks * 64 + lane) * 68;
            const float* k1p = k0p + 32 * 68;
            const float* q0 = qs + (rg * 4 + 0) * 68;
            const float* q1 = qs + (rg * 4 + 1) * 68;
            const float* q2 = qs + (rg * 4 + 2) * 68;
            const float* q3 = qs + (rg * 4 + 3) * 68;
            #pragma unroll
            for (int d = 0; d < DH; d += 4) {
                float4 k0 = *(const float4*)(k0p + d);
                float4 k1 = *(const float4*)(k1p + d);
                float4 a;
                a = *(const float4*)(q0 + d);
                acc[0][0] += a.x*k0.x + a.y*k0.y + a.z*k0.z + a.w*k0.w;
                acc[0][1] += a.x*k1.x + a.y*k1.y + a.z*k1.z + a.w*k1.w;
                a = *(const float4*)(q1 + d);
                acc[1][0] += a.x*k0.x + a.y*k0.y + a.z*k0.z + a.w*k0.w;
                acc[1][1] += a.x*k1.x + a.y*k1.y + a.z*k1.z + a.w*k1.w;
                a = *(const float4*)(q2 + d);
                acc[2][0] += a.x*k0.x + a.y*k0.y + a.z*k0.z + a.w*k0.w;
                acc[2][1] += a.x*k1.x + a.y*k1.y + a.z*k1.z + a.w*k1.w;
                a = *(const float4*)(q3 + d);
                acc[3][0] += a.x*k0.x + a.y*k0.y + a.z*k0.z + a.w*k0.w;
                acc[3][1] += a.x*k1.x + a.y*k1.y + a.z*k1.z + a.w*k1.w;
            }
            const int gj0 = jt + ks * 64 + lane;
            const int gj1 = gj0 + 32;
            #pragma unroll
            for (int r = 0; r < 4; r++) {
                const int row = rg * 4 + r;
                const int gi  = i0 + row;
                sc[row * SQ + gj0] = (gj0 <= gi) ? fmaf(slope, (float)(gj0 - gi), acc[r][0] * inv_scale) : -INFINITY;
                sc[row * SQ + gj1] = (gj1 <= gi) ? fmaf(slope, (float)(gj1 - gi), acc[r][1] * inv_scale) : -INFINITY;
            }
        }
        __syncthreads();
    }

    // ======================= softmax (warp w owns row w) =======================
    {
        float* row = sc + w * SQ;
        float mx = -INFINITY;
        for (int j = lane * 4; j < jend; j += 128) {
            float4 v = *(const float4*)(row + j);
            mx = fmaxf(mx, fmaxf(fmaxf(v.x, v.y), fmaxf(v.z, v.w)));
        }
        #pragma unroll
        for (int o = 16; o; o >>= 1) mx = fmaxf(mx, __shfl_xor_sync(0xffffffffu, mx, o));
        float sum = 0.f;
        for (int j = lane * 4; j < jend; j += 128) {
            float4 v = *(const float4*)(row + j);
            v.x = __expf(v.x - mx); v.y = __expf(v.y - mx);
            v.z = __expf(v.z - mx); v.w = __expf(v.w - mx);
            *(float4*)(row + j) = v;
            sum += v.x + v.y + v.z + v.w;
        }
        #pragma unroll
        for (int o = 16; o; o >>= 1) sum += __shfl_xor_sync(0xffffffffu, sum, o);
        const float inv = 1.0f / sum;
        if (lane == 0) sinv[w] = inv;

        if (write_attn) {
            float* arow = attn + ((size_t)((b * HH + h) * SQ + i0 + w)) * SQ;
            for (int j = lane * 4; j < jend; j += 128) {
                float4 v = *(const float4*)(row + j);
                v.x *= inv; v.y *= inv; v.z *= inv; v.w *= inv;
                *(float4*)(arow + j) = v;
            }
            const float4 z = make_float4(0.f, 0.f, 0.f, 0.f);
            for (int j = jend + lane * 4; j < SQ; j += 128)
                *(float4*)(arow + j) = z;
        }
    }

    // ======================= PV =======================
    // V^T tile: kq reused as vq[d][j], stride 260.
    float a[4][2] = {};
    for (int jt = 0; jt < jend; jt += KT) {
        const int ktile = min(KT, jend - jt);
        __syncthreads();
        for (int idx = tid; idx < 16 * KT; idx += 512) {
            int j = idx & (KT - 1), dq = idx >> 8;      // dq 0..15
            if (j < ktile) {
                float4 v = *(const float4*)&qkv[(size_t)(b * SQ + jt + j) * (3 * EE) + 2 * EE + h * DH + dq * 4];
                kq[(dq * 4 + 0) * 260 + j] = v.x;
                kq[(dq * 4 + 1) * 260 + j] = v.y;
                kq[(dq * 4 + 2) * 260 + j] = v.z;
                kq[(dq * 4 + 3) * 260 + j] = v.w;
            }
        }
        __syncthreads();

        if (ks * 64 < ktile) {
            const float* v0p = kq + lane * 260 + ks * 64;
            const float* v1p = kq + (lane + 32) * 260 + ks * 64;
            const float* p0 = sc + (rg * 4 + 0) * SQ + jt + ks * 64;
            const float* p1 = sc + (rg * 4 + 1) * SQ + jt + ks * 64;
            const float* p2 = sc + (rg * 4 + 2) * SQ + jt + ks * 64;
            const float* p3 = sc + (rg * 4 + 3) * SQ + jt + ks * 64;
            #pragma unroll
            for (int jj = 0; jj < 64; jj += 4) {
                float4 v0 = *(const float4*)(v0p + jj);
                float4 v1 = *(const float4*)(v1p + jj);
                float4 p;
                p = *(const float4*)(p0 + jj);
                a[0][0] += p.x*v0.x + p.y*v0.y + p.z*v0.z + p.w*v0.w;
                a[0][1] += p.x*v1.x + p.y*v1.y + p.z*v1.z + p.w*v1.w;
                p = *(const float4*)(p1 + jj);
                a[1][0] += p.x*v0.x + p.y*v0.y + p.z*v0.z + p.w*v0.w;
                a[1][1] += p.x*v1.x + p.y*v1.y + p.z*v1.z + p.w*v1.w;
                p = *(const float4*)(p2 + jj);
                a[2][0] += p.x*v0.x + p.y*v0.y + p.z*v0.z + p.w*v0.w;
                a[2][1] += p.x*v1.x + p.y*v1.y + p.z*v1.z + p.w*v1.w;
                p = *(const float4*)(p3 + jj);
                a[3][0] += p.x*v0.x + p.y*v0.y + p.z*v0.z + p.w*v0.w;
                a[3][1] += p.x*v1.x + p.y*v1.y + p.z*v1.z + p.w*v1.w;
            }
        }
    }

    // --- reduce partials across the 4 key-slab warps ---
    __syncthreads();
    float* red = kq;   // 3 * 16 * 64 floats
    if (ks > 0) {
        #pragma unroll
        for (int r = 0; r < 4; r++) {
            red[((ks - 1) * 16 + rg * 4 + r) * 64 + lane]      = a[r][0];
            red[((ks - 1) * 16 + rg * 4 + r) * 64 + lane + 32] = a[r][1];
        }
    }
    __syncthreads();
    if (ks == 0) {
        #pragma unroll
        for (int r = 0; r < 4; r++) {
            const int row = rg * 4 + r;
            const float inv = sinv[row];
            float s0 = a[r][0] + red[(0 * 16 + row) * 64 + lane]
                               + red[(1 * 16 + row) * 64 + lane]
                               + red[(2 * 16 + row) * 64 + lane];
            float s1 = a[r][1] + red[(0 * 16 + row) * 64 + lane + 32]
                               + red[(1 * 16 + row) * 64 + lane + 32]
                               + red[(2 * 16 + row) * 64 + lane + 32];
            out[(size_t)(b * SQ + i0 + row) * EE + h * DH + lane]      = s0 * inv;
            out[(size_t)(b * SQ + i0 + row) * EE + h * DH + lane + 32] = s1 * inv;
        }
    }
}

// ---------------------------------------------------------------------------
extern "C" void kernel_launch(void* const* d_in, const int* in_sizes, int n_in,
                              void* d_out, int out_size)
{
    const float* x = (const float*)d_in[0];
    const float* W = (const float*)d_in[1];
    float* out = (float*)d_out;

    const long out_elems  = (long)BB * SQ * EE;               // 8,388,608
    const long attn_elems = (long)BB * HH * SQ * SQ;          // 268,435,456
    int write_attn = ((long)out_size >= out_elems + attn_elems) ? 1 : 0;
    float* attn = write_attn ? (out + out_elems) : nullptr;

    float* qkv;
    cudaGetSymbolAddress((void**)&qkv, g_qkv);

    // QKV projection
    {
        dim3 grid(GN / 128, GM / 128);
        qkv_gemm_kernel<<<grid, 256>>>(x, W, qkv);
    }

    // Fused attention
    {
        int smem_bytes = (ROWS * SQ + 17408 + ROWS * 68 + 16) * (int)sizeof(float);
        cudaFuncSetAttribute(attn_kernel, cudaFuncAttributeMaxDynamicSharedMemorySize, smem_bytes);
        dim3 grid(SQ / ROWS, HH, BB);
        attn_kernel<<<grid, 512, smem_bytes>>>(qkv, out, attn, write_attn);
    }
}

// round 7
// speedup vs baseline: 1.9734x; 1.2569x over previous
#include <cuda_runtime.h>
#include <math.h>
#include <stdint.h>

#define BB 4
#define SQ 2048
#define EE 1024
#define HH 16
#define DH 64
#define ROWS 16
#define KT 256

#define GM (BB*SQ)     // 8192
#define GN (3*EE)      // 3072
#define GK (EE)        // 1024

// GEMM tiling
#define TM 128
#define TN 128
#define TKS 32
#define PAD 36         // smem row pitch in floats (bank-conflict-free fragments)
#define ABUF (TM*PAD)  // 4608 floats per buffer per operand

// Scratch for qkv projection result: [B, S, 3E] = 100.7 MB
__device__ float g_qkv[(size_t)BB * SQ * 3 * EE];

__device__ __forceinline__ uint32_t f2tf32(float x) {
    uint32_t r;
    asm("cvt.rna.tf32.f32 %0, %1;" : "=r"(r) : "f"(x));
    return r;
}

// ---------------------------------------------------------------------------
// QKV GEMM (TF32 tensor cores): C[M,N] = A[M,K] @ W[N,K]^T
// 128x128 CTA tile, 8 warps (warp tile 32x64), K-slab 32,
// cp.async double-buffered smem, mma.sync.m16n8k8.tf32.
// ---------------------------------------------------------------------------
__global__ __launch_bounds__(256, 2) void qkv_gemm_tf32(
    const float* __restrict__ A, const float* __restrict__ W, float* __restrict__ C)
{
    extern __shared__ float gs[];
    float* As = gs;               // [2][ABUF]
    float* Bs = gs + 2 * ABUF;    // [2][ABUF]

    const int tid  = threadIdx.x;
    const int lane = tid & 31;
    const int wid  = tid >> 5;
    const int wm   = wid & 3;          // warp m index (0..3) -> rows wm*32
    const int wn   = wid >> 2;         // warp n index (0..1) -> cols wn*64
    const int g    = lane >> 2;        // group id 0..7
    const int tig  = lane & 3;         // thread-in-group 0..3
    const int m0   = blockIdx.y * TM;
    const int n0   = blockIdx.x * TN;

    const uint32_t s_base = (uint32_t)__cvta_generic_to_shared(gs);

    float acc[2][8][4] = {};

    // async-load one K-slab of A and W into buffer `buf`
    auto issue = [&](int s, int buf) {
        const int k0 = s * TKS;
        #pragma unroll
        for (int i = 0; i < 4; i++) {
            int c   = tid + i * 256;       // 0..1023
            int row = c >> 3;              // 0..127
            int kc  = (c & 7) * 4;         // float offset within slab
            const float* srcA = A + (size_t)(m0 + row) * GK + k0 + kc;
            uint32_t dstA = s_base + (uint32_t)(buf * ABUF + row * PAD + kc) * 4u;
            asm volatile("cp.async.cg.shared.global [%0], [%1], 16;\n" :: "r"(dstA), "l"(srcA));
            const float* srcB = W + (size_t)(n0 + row) * GK + k0 + kc;
            uint32_t dstB = s_base + (uint32_t)(2 * ABUF * 4u) + (uint32_t)(buf * ABUF + row * PAD + kc) * 4u;
            asm volatile("cp.async.cg.shared.global [%0], [%1], 16;\n" :: "r"(dstB), "l"(srcB));
        }
        asm volatile("cp.async.commit_group;\n" ::);
    };

    const int NS = GK / TKS;   // 32 slabs
    issue(0, 0);

    for (int s = 0; s < NS; s++) {
        const int cur = s & 1;
        if (s + 1 < NS) {
            issue(s + 1, cur ^ 1);
            asm volatile("cp.async.wait_group 1;\n" ::);
        } else {
            asm volatile("cp.async.wait_group 0;\n" ::);
        }
        __syncthreads();

        const float* Ab = As + cur * ABUF + (wm * 32) * PAD;
        const float* Bb = Bs + cur * ABUF + (wn * 64) * PAD;

        #pragma unroll
        for (int kk = 0; kk < TKS; kk += 8) {
            uint32_t bf[8][2];
            #pragma unroll
            for (int nt = 0; nt < 8; nt++) {
                bf[nt][0] = f2tf32(Bb[(nt * 8 + g) * PAD + kk + tig]);
                bf[nt][1] = f2tf32(Bb[(nt * 8 + g) * PAD + kk + tig + 4]);
            }
            #pragma unroll
            for (int mt = 0; mt < 2; mt++) {
                uint32_t af[4];
                af[0] = f2tf32(Ab[(mt * 16 + g) * PAD     + kk + tig]);
                af[1] = f2tf32(Ab[(mt * 16 + g + 8) * PAD + kk + tig]);
                af[2] = f2tf32(Ab[(mt * 16 + g) * PAD     + kk + tig + 4]);
                af[3] = f2tf32(Ab[(mt * 16 + g + 8) * PAD + kk + tig + 4]);
                #pragma unroll
                for (int nt = 0; nt < 8; nt++) {
                    asm volatile(
                        "mma.sync.aligned.m16n8k8.row.col.f32.tf32.tf32.f32 "
                        "{%0,%1,%2,%3}, {%4,%5,%6,%7}, {%8,%9}, {%0,%1,%2,%3};\n"
                        : "+f"(acc[mt][nt][0]), "+f"(acc[mt][nt][1]),
                          "+f"(acc[mt][nt][2]), "+f"(acc[mt][nt][3])
                        : "r"(af[0]), "r"(af[1]), "r"(af[2]), "r"(af[3]),
                          "r"(bf[nt][0]), "r"(bf[nt][1]));
                }
            }
        }
        __syncthreads();
    }

    // epilogue: c0:(g, 2tig) c1:(g, 2tig+1) c2/c3: row+8
    #pragma unroll
    for (int mt = 0; mt < 2; mt++) {
        #pragma unroll
        for (int nt = 0; nt < 8; nt++) {
            int r0 = m0 + wm * 32 + mt * 16 + g;
            int cc = n0 + wn * 64 + nt * 8 + 2 * tig;
            *(float2*)&C[(size_t)r0 * GN + cc]       = make_float2(acc[mt][nt][0], acc[mt][nt][1]);
            *(float2*)&C[(size_t)(r0 + 8) * GN + cc] = make_float2(acc[mt][nt][2], acc[mt][nt][3]);
        }
    }
}

// ---------------------------------------------------------------------------
// Fused causal ALiBi attention, register-blocked 4 rows x 2 keys per warp.
// (unchanged from the 3396us version)
// ---------------------------------------------------------------------------
__global__ __launch_bounds__(512, 1) void attn_kernel(
    const float* __restrict__ qkv, float* __restrict__ out,
    float* __restrict__ attn, int write_attn)
{
    extern __shared__ float smem[];
    float* sc  = smem;                     // 16 * 2048
    float* kq  = sc + ROWS * SQ;           // 17408 floats (K tile / V^T tile / reduce)
    float* qs  = kq + 17408;               // 16 * 68
    float* sinv = qs + ROWS * 68;          // 16

    const int i0 = (gridDim.x - 1 - blockIdx.x) * ROWS;   // longest tiles first
    const int h  = blockIdx.y;
    const int b  = blockIdx.z;
    const int tid = threadIdx.x;
    const int lane = tid & 31;
    const int w = tid >> 5;                // warp 0..15
    const int rg = w & 3;                  // row group: rows rg*4 .. rg*4+3
    const int ks = w >> 2;                 // key slab: keys ks*64 + lane, +32

    const float slope = exp2f(-0.5f * (float)(h + 1));   // 1/(2^8)^((h+1)/16)
    const float inv_scale = 1.0f / 32.0f;                // 1/sqrt(E)

    // --- load Q (16 x 64), q chunk = middle third of qkv ---
    if (tid < 256) {
        int r = tid >> 4, dc = (tid & 15) * 4;
        float4 v = *(const float4*)&qkv[(size_t)(b * SQ + i0 + r) * (3 * EE) + EE + h * DH + dc];
        *(float4*)&qs[r * 68 + dc] = v;
    }
    __syncthreads();

    const int jend = ((i0 + ROWS - 1) / 64 + 1) * 64;   // causal extent, mult of 64

    // ======================= scores =======================
    for (int jt = 0; jt < jend; jt += KT) {
        const int ktile = min(KT, jend - jt);           // multiple of 64
        for (int idx = tid; idx < ktile * 16; idx += 512) {
            int jj = idx >> 4, dc = (idx & 15) * 4;
            float4 v = *(const float4*)&qkv[(size_t)(b * SQ + jt + jj) * (3 * EE) + h * DH + dc];
            *(float4*)&kq[jj * 68 + dc] = v;
        }
        __syncthreads();

        if (ks * 64 < ktile) {
            float acc[4][2] = {};
            const float* k0p = kq + (ks * 64 + lane) * 68;
            const float* k1p = k0p + 32 * 68;
            const float* q0 = qs + (rg * 4 + 0) * 68;
            const float* q1 = qs + (rg * 4 + 1) * 68;
            const float* q2 = qs + (rg * 4 + 2) * 68;
            const float* q3 = qs + (rg * 4 + 3) * 68;
            #pragma unroll
            for (int d = 0; d < DH; d += 4) {
                float4 k0 = *(const float4*)(k0p + d);
                float4 k1 = *(const float4*)(k1p + d);
                float4 a;
                a = *(const float4*)(q0 + d);
                acc[0][0] += a.x*k0.x + a.y*k0.y + a.z*k0.z + a.w*k0.w;
                acc[0][1] += a.x*k1.x + a.y*k1.y + a.z*k1.z + a.w*k1.w;
                a = *(const float4*)(q1 + d);
                acc[1][0] += a.x*k0.x + a.y*k0.y + a.z*k0.z + a.w*k0.w;
                acc[1][1] += a.x*k1.x + a.y*k1.y + a.z*k1.z + a.w*k1.w;
                a = *(const float4*)(q2 + d);
                acc[2][0] += a.x*k0.x + a.y*k0.y + a.z*k0.z + a.w*k0.w;
                acc[2][1] += a.x*k1.x + a.y*k1.y + a.z*k1.z + a.w*k1.w;
                a = *(const float4*)(q3 + d);
                acc[3][0] += a.x*k0.x + a.y*k0.y + a.z*k0.z + a.w*k0.w;
                acc[3][1] += a.x*k1.x + a.y*k1.y + a.z*k1.z + a.w*k1.w;
            }
            const int gj0 = jt + ks * 64 + lane;
            const int gj1 = gj0 + 32;
            #pragma unroll
            for (int r = 0; r < 4; r++) {
                const int row = rg * 4 + r;
                const int gi  = i0 + row;
                sc[row * SQ + gj0] = (gj0 <= gi) ? fmaf(slope, (float)(gj0 - gi), acc[r][0] * inv_scale) : -INFINITY;
                sc[row * SQ + gj1] = (gj1 <= gi) ? fmaf(slope, (float)(gj1 - gi), acc[r][1] * inv_scale) : -INFINITY;
            }
        }
        __syncthreads();
    }

    // ======================= softmax (warp w owns row w) =======================
    {
        float* row = sc + w * SQ;
        float mx = -INFINITY;
        for (int j = lane * 4; j < jend; j += 128) {
            float4 v = *(const float4*)(row + j);
            mx = fmaxf(mx, fmaxf(fmaxf(v.x, v.y), fmaxf(v.z, v.w)));
        }
        #pragma unroll
        for (int o = 16; o; o >>= 1) mx = fmaxf(mx, __shfl_xor_sync(0xffffffffu, mx, o));
        float sum = 0.f;
        for (int j = lane * 4; j < jend; j += 128) {
            float4 v = *(const float4*)(row + j);
            v.x = __expf(v.x - mx); v.y = __expf(v.y - mx);
            v.z = __expf(v.z - mx); v.w = __expf(v.w - mx);
            *(float4*)(row + j) = v;
            sum += v.x + v.y + v.z + v.w;
        }
        #pragma unroll
        for (int o = 16; o; o >>= 1) sum += __shfl_xor_sync(0xffffffffu, sum, o);
        const float inv = 1.0f / sum;
        if (lane == 0) sinv[w] = inv;

        if (write_attn) {
            float* arow = attn + ((size_t)((b * HH + h) * SQ + i0 + w)) * SQ;
            for (int j = lane * 4; j < jend; j += 128) {
                float4 v = *(const float4*)(row + j);
                v.x *= inv; v.y *= inv; v.z *= inv; v.w *= inv;
                *(float4*)(arow + j) = v;
            }
            const float4 z = make_float4(0.f, 0.f, 0.f, 0.f);
            for (int j = jend + lane * 4; j < SQ; j += 128)
                *(float4*)(arow + j) = z;
        }
    }

    // ======================= PV =======================
    float a[4][2] = {};
    for (int jt = 0; jt < jend; jt += KT) {
        const int ktile = min(KT, jend - jt);
        __syncthreads();
        for (int idx = tid; idx < 16 * KT; idx += 512) {
            int j = idx & (KT - 1), dq = idx >> 8;      // dq 0..15
            if (j < ktile) {
                float4 v = *(const float4*)&qkv[(size_t)(b * SQ + jt + j) * (3 * EE) + 2 * EE + h * DH + dq * 4];
                kq[(dq * 4 + 0) * 260 + j] = v.x;
                kq[(dq * 4 + 1) * 260 + j] = v.y;
                kq[(dq * 4 + 2) * 260 + j] = v.z;
                kq[(dq * 4 + 3) * 260 + j] = v.w;
            }
        }
        __syncthreads();

        if (ks * 64 < ktile) {
            const float* v0p = kq + lane * 260 + ks * 64;
            const float* v1p = kq + (lane + 32) * 260 + ks * 64;
            const float* p0 = sc + (rg * 4 + 0) * SQ + jt + ks * 64;
            const float* p1 = sc + (rg * 4 + 1) * SQ + jt + ks * 64;
            const float* p2 = sc + (rg * 4 + 2) * SQ + jt + ks * 64;
            const float* p3 = sc + (rg * 4 + 3) * SQ + jt + ks * 64;
            #pragma unroll
            for (int jj = 0; jj < 64; jj += 4) {
                float4 v0 = *(const float4*)(v0p + jj);
                float4 v1 = *(const float4*)(v1p + jj);
                float4 p;
                p = *(const float4*)(p0 + jj);
                a[0][0] += p.x*v0.x + p.y*v0.y + p.z*v0.z + p.w*v0.w;
                a[0][1] += p.x*v1.x + p.y*v1.y + p.z*v1.z + p.w*v1.w;
                p = *(const float4*)(p1 + jj);
                a[1][0] += p.x*v0.x + p.y*v0.y + p.z*v0.z + p.w*v0.w;
                a[1][1] += p.x*v1.x + p.y*v1.y + p.z*v1.z + p.w*v1.w;
                p = *(const float4*)(p2 + jj);
                a[2][0] += p.x*v0.x + p.y*v0.y + p.z*v0.z + p.w*v0.w;
                a[2][1] += p.x*v1.x + p.y*v1.y + p.z*v1.z + p.w*v1.w;
                p = *(const float4*)(p3 + jj);
                a[3][0] += p.x*v0.x + p.y*v0.y + p.z*v0.z + p.w*v0.w;
                a[3][1] += p.x*v1.x + p.y*v1.y + p.z*v1.z + p.w*v1.w;
            }
        }
    }

    // --- reduce partials across the 4 key-slab warps ---
    __syncthreads();
    float* red = kq;   // 3 * 16 * 64 floats
    if (ks > 0) {
        #pragma unroll
        for (int r = 0; r < 4; r++) {
            red[((ks - 1) * 16 + rg * 4 + r) * 64 + lane]      = a[r][0];
            red[((ks - 1) * 16 + rg * 4 + r) * 64 + lane + 32] = a[r][1];
        }
    }
    __syncthreads();
    if (ks == 0) {
        #pragma unroll
        for (int r = 0; r < 4; r++) {
            const int row = rg * 4 + r;
            const float inv = sinv[row];
            float s0 = a[r][0] + red[(0 * 16 + row) * 64 + lane]
                               + red[(1 * 16 + row) * 64 + lane]
                               + red[(2 * 16 + row) * 64 + lane];
            float s1 = a[r][1] + red[(0 * 16 + row) * 64 + lane + 32]
                               + red[(1 * 16 + row) * 64 + lane + 32]
                               + red[(2 * 16 + row) * 64 + lane + 32];
            out[(size_t)(b * SQ + i0 + row) * EE + h * DH + lane]      = s0 * inv;
            out[(size_t)(b * SQ + i0 + row) * EE + h * DH + lane + 32] = s1 * inv;
        }
    }
}

// ---------------------------------------------------------------------------
extern "C" void kernel_launch(void* const* d_in, const int* in_sizes, int n_in,
                              void* d_out, int out_size)
{
    const float* x = (const float*)d_in[0];
    const float* W = (const float*)d_in[1];
    float* out = (float*)d_out;

    const long out_elems  = (long)BB * SQ * EE;               // 8,388,608
    const long attn_elems = (long)BB * HH * SQ * SQ;          // 268,435,456
    int write_attn = ((long)out_size >= out_elems + attn_elems) ? 1 : 0;
    float* attn = write_attn ? (out + out_elems) : nullptr;

    float* qkv;
    cudaGetSymbolAddress((void**)&qkv, g_qkv);

    // QKV projection (TF32 tensor cores)
    {
        int gemm_smem = 4 * ABUF * (int)sizeof(float);   // 73728 B
        cudaFuncSetAttribute(qkv_gemm_tf32, cudaFuncAttributeMaxDynamicSharedMemorySize, gemm_smem);
        dim3 grid(GN / TN, GM / TM);
        qkv_gemm_tf32<<<grid, 256, gemm_smem>>>(x, W, qkv);
    }

    // Fused attention
    {
        int smem_bytes = (ROWS * SQ + 17408 + ROWS * 68 + 16) * (int)sizeof(float);
        cudaFuncSetAttribute(attn_kernel, cudaFuncAttributeMaxDynamicSharedMemorySize, smem_bytes);
        dim3 grid(SQ / ROWS, HH, BB);
        attn_kernel<<<grid, 512, smem_bytes>>>(qkv, out, attn, write_attn);
    }
}

// round 8
// speedup vs baseline: 3.2804x; 1.6623x over previous
#include <cuda_runtime.h>
#include <math.h>
#include <stdint.h>

#define BB 4
#define SQ 2048
#define EE 1024
#define HH 16
#define DH 64
#define ROWS 16
#define KT 256

#define GM (BB*SQ)     // 8192
#define GN (3*EE)      // 3072
#define GK (EE)        // 1024

// GEMM tiling
#define TM 128
#define TN 128
#define TKS 32
#define PAD 36
#define ABUF (TM*PAD)

#define SCP 2052       // sc row pitch (mod 32 banks = 4)

// Scratch: q,k [B,H,S,Dh]; v transposed [B,H,Dh,S]
__device__ float g_q[(size_t)BB * HH * SQ * DH];
__device__ float g_k[(size_t)BB * HH * SQ * DH];
__device__ float g_v[(size_t)BB * HH * DH * SQ];

__device__ __forceinline__ uint32_t f2tf32(float x) {
    uint32_t r;
    asm("cvt.rna.tf32.f32 %0, %1;" : "=r"(r) : "f"(x));
    return r;
}

#define MMA_TF32(acc, a0, a1, a2, a3, b0, b1)                                \
    asm volatile(                                                            \
        "mma.sync.aligned.m16n8k8.row.col.f32.tf32.tf32.f32 "                \
        "{%0,%1,%2,%3}, {%4,%5,%6,%7}, {%8,%9}, {%0,%1,%2,%3};\n"            \
        : "+f"(acc[0]), "+f"(acc[1]), "+f"(acc[2]), "+f"(acc[3])             \
        : "r"(a0), "r"(a1), "r"(a2), "r"(a3), "r"(b0), "r"(b1))

// ---------------------------------------------------------------------------
// QKV GEMM (TF32): computes qkv = x @ W^T, scatters into g_k/g_q/g_v.
// ---------------------------------------------------------------------------
__global__ __launch_bounds__(256, 2) void qkv_gemm_tf32(
    const float* __restrict__ A, const float* __restrict__ W,
    float* __restrict__ gq, float* __restrict__ gk, float* __restrict__ gv)
{
    extern __shared__ float gs[];
    float* As = gs;
    float* Bs = gs + 2 * ABUF;

    const int tid  = threadIdx.x;
    const int lane = tid & 31;
    const int wid  = tid >> 5;
    const int wm   = wid & 3;
    const int wn   = wid >> 2;
    const int g    = lane >> 2;
    const int tig  = lane & 3;
    const int m0   = blockIdx.y * TM;
    const int n0   = blockIdx.x * TN;

    const uint32_t s_base = (uint32_t)__cvta_generic_to_shared(gs);

    float acc[2][8][4] = {};

    auto issue = [&](int s, int buf) {
        const int k0 = s * TKS;
        #pragma unroll
        for (int i = 0; i < 4; i++) {
            int c   = tid + i * 256;
            int row = c >> 3;
            int kc  = (c & 7) * 4;
            const float* srcA = A + (size_t)(m0 + row) * GK + k0 + kc;
            uint32_t dstA = s_base + (uint32_t)(buf * ABUF + row * PAD + kc) * 4u;
            asm volatile("cp.async.cg.shared.global [%0], [%1], 16;\n" :: "r"(dstA), "l"(srcA));
            const float* srcB = W + (size_t)(n0 + row) * GK + k0 + kc;
            uint32_t dstB = s_base + (uint32_t)(2 * ABUF * 4u) + (uint32_t)(buf * ABUF + row * PAD + kc) * 4u;
            asm volatile("cp.async.cg.shared.global [%0], [%1], 16;\n" :: "r"(dstB), "l"(srcB));
        }
        asm volatile("cp.async.commit_group;\n" ::);
    };

    const int NS = GK / TKS;
    issue(0, 0);

    for (int s = 0; s < NS; s++) {
        const int cur = s & 1;
        if (s + 1 < NS) {
            issue(s + 1, cur ^ 1);
            asm volatile("cp.async.wait_group 1;\n" ::);
        } else {
            asm volatile("cp.async.wait_group 0;\n" ::);
        }
        __syncthreads();

        const float* Ab = As + cur * ABUF + (wm * 32) * PAD;
        const float* Bb = Bs + cur * ABUF + (wn * 64) * PAD;

        #pragma unroll
        for (int kk = 0; kk < TKS; kk += 8) {
            uint32_t bf[8][2];
            #pragma unroll
            for (int nt = 0; nt < 8; nt++) {
                bf[nt][0] = f2tf32(Bb[(nt * 8 + g) * PAD + kk + tig]);
                bf[nt][1] = f2tf32(Bb[(nt * 8 + g) * PAD + kk + tig + 4]);
            }
            #pragma unroll
            for (int mt = 0; mt < 2; mt++) {
                uint32_t af[4];
                af[0] = f2tf32(Ab[(mt * 16 + g) * PAD     + kk + tig]);
                af[1] = f2tf32(Ab[(mt * 16 + g + 8) * PAD + kk + tig]);
                af[2] = f2tf32(Ab[(mt * 16 + g) * PAD     + kk + tig + 4]);
                af[3] = f2tf32(Ab[(mt * 16 + g + 8) * PAD + kk + tig + 4]);
                #pragma unroll
                for (int nt = 0; nt < 8; nt++)
                    MMA_TF32(acc[mt][nt], af[0], af[1], af[2], af[3], bf[nt][0], bf[nt][1]);
            }
        }
        __syncthreads();
    }

    // epilogue: scatter to g_k (chunk 0), g_q (chunk 1), g_v transposed (chunk 2)
    #pragma unroll
    for (int mt = 0; mt < 2; mt++) {
        #pragma unroll
        for (int nt = 0; nt < 8; nt++) {
            const int cc    = n0 + wn * 64 + nt * 8 + 2 * tig;
            const int chunk = cc >> 10;
            const int hd    = (cc & 1023) >> 6;
            const int d     = cc & 63;
            #pragma unroll
            for (int half = 0; half < 2; half++) {
                const int r = m0 + wm * 32 + mt * 16 + g + half * 8;
                const int b = r >> 11, srow = r & 2047;
                const float c0 = acc[mt][nt][half * 2 + 0];
                const float c1 = acc[mt][nt][half * 2 + 1];
                const size_t bh = (size_t)(b * HH + hd);
                if (chunk == 0) {
                    *(float2*)&gk[(bh * SQ + srow) * DH + d] = make_float2(c0, c1);
                } else if (chunk == 1) {
                    *(float2*)&gq[(bh * SQ + srow) * DH + d] = make_float2(c0, c1);
                } else {
                    gv[(bh * DH + d) * SQ + srow]     = c0;
                    gv[(bh * DH + d + 1) * SQ + srow] = c1;
                }
            }
        }
    }
}

// ---------------------------------------------------------------------------
// Fused causal ALiBi attention with TF32 MMA scores + PV.
// One CTA per (b, h, 16-row query tile). 512 threads = 16 warps.
// smem: sc[16][2052] + kq[17408] (K tile / V^T tile / reduce) + qs + sinv
// ---------------------------------------------------------------------------
__global__ __launch_bounds__(512, 1) void attn_kernel(
    const float* __restrict__ gq, const float* __restrict__ gk,
    const float* __restrict__ gv, float* __restrict__ out,
    float* __restrict__ attn, int write_attn)
{
    extern __shared__ float smem[];
    float* sc   = smem;                    // 16 * SCP
    float* kq   = sc + ROWS * SCP;         // 17408 floats
    float* qs   = kq + 17408;              // 16 * 68
    float* sinv = qs + ROWS * 68;          // 16

    const int i0 = (gridDim.x - 1 - blockIdx.x) * ROWS;   // longest tiles first
    const int h  = blockIdx.y;
    const int b  = blockIdx.z;
    const int tid  = threadIdx.x;
    const int lane = tid & 31;
    const int w    = tid >> 5;             // warp 0..15
    const int g    = lane >> 2;            // 0..7
    const int tig  = lane & 3;             // 0..3

    const size_t bh   = (size_t)(b * HH + h);
    const float slope = exp2f(-0.5f * (float)(h + 1));
    const float inv_scale = 1.0f / 32.0f;

    // --- load Q (16 x 64) ---
    if (tid < 256) {
        int r = tid >> 4, dc = (tid & 15) * 4;
        float4 v = *(const float4*)&gq[(bh * SQ + i0 + r) * DH + dc];
        *(float4*)&qs[r * 68 + dc] = v;
    }
    __syncthreads();

    const int jend = ((i0 + ROWS - 1) / 64 + 1) * 64;

    // --- preload Q fragments (rows g, g+8), tf32 ---
    uint32_t qa[8][4];
    #pragma unroll
    for (int kk = 0; kk < 8; kk++) {
        qa[kk][0] = f2tf32(qs[g * 68       + kk * 8 + tig]);
        qa[kk][1] = f2tf32(qs[(g + 8) * 68 + kk * 8 + tig]);
        qa[kk][2] = f2tf32(qs[g * 68       + kk * 8 + tig + 4]);
        qa[kk][3] = f2tf32(qs[(g + 8) * 68 + kk * 8 + tig + 4]);
    }

    // ======================= scores (MMA) =======================
    // warp w covers keys [w*16, w*16+16) within each 256-key pass.
    for (int jt = 0; jt < jend; jt += KT) {
        const int ktile = min(KT, jend - jt);
        for (int idx = tid; idx < ktile * 16; idx += 512) {
            int key = idx >> 4, dc = (idx & 15) * 4;
            float4 v = *(const float4*)&gk[(bh * SQ + jt + key) * DH + dc];
            *(float4*)&kq[key * 68 + dc] = v;
        }
        __syncthreads();

        const int kb = w * 16;
        if (kb < ktile) {
            float acc[2][4] = {};
            #pragma unroll
            for (int kk = 0; kk < 8; kk++) {
                #pragma unroll
                for (int nt = 0; nt < 2; nt++) {
                    uint32_t b0 = f2tf32(kq[(kb + nt * 8 + g) * 68 + kk * 8 + tig]);
                    uint32_t b1 = f2tf32(kq[(kb + nt * 8 + g) * 68 + kk * 8 + tig + 4]);
                    MMA_TF32(acc[nt], qa[kk][0], qa[kk][1], qa[kk][2], qa[kk][3], b0, b1);
                }
            }
            #pragma unroll
            for (int nt = 0; nt < 2; nt++) {
                const int j0 = jt + kb + nt * 8 + 2 * tig;
                #pragma unroll
                for (int half = 0; half < 2; half++) {
                    const int row = g + half * 8;
                    const int gi  = i0 + row;
                    float v0 = (j0     <= gi) ? fmaf(slope, (float)(j0 - gi),     acc[nt][half*2+0] * inv_scale) : -INFINITY;
                    float v1 = (j0 + 1 <= gi) ? fmaf(slope, (float)(j0 + 1 - gi), acc[nt][half*2+1] * inv_scale) : -INFINITY;
                    *(float2*)&sc[row * SCP + j0] = make_float2(v0, v1);
                }
            }
        }
        __syncthreads();
    }

    // ======================= softmax (warp w owns row w) =======================
    {
        float* row = sc + w * SCP;
        float mx = -INFINITY;
        for (int j = lane * 4; j < jend; j += 128) {
            float4 v = *(const float4*)(row + j);
            mx = fmaxf(mx, fmaxf(fmaxf(v.x, v.y), fmaxf(v.z, v.w)));
        }
        #pragma unroll
        for (int o = 16; o; o >>= 1) mx = fmaxf(mx, __shfl_xor_sync(0xffffffffu, mx, o));
        float sum = 0.f;
        for (int j = lane * 4; j < jend; j += 128) {
            float4 v = *(const float4*)(row + j);
            v.x = __expf(v.x - mx); v.y = __expf(v.y - mx);
            v.z = __expf(v.z - mx); v.w = __expf(v.w - mx);
            *(float4*)(row + j) = v;
            sum += v.x + v.y + v.z + v.w;
        }
        #pragma unroll
        for (int o = 16; o; o >>= 1) sum += __shfl_xor_sync(0xffffffffu, sum, o);
        const float inv = 1.0f / sum;
        if (lane == 0) sinv[w] = inv;

        if (write_attn) {
            float* arow = attn + (bh * SQ + i0 + w) * SQ;
            for (int j = lane * 4; j < jend; j += 128) {
                float4 v = *(const float4*)(row + j);
                v.x *= inv; v.y *= inv; v.z *= inv; v.w *= inv;
                *(float4*)(arow + j) = v;
            }
            const float4 z = make_float4(0.f, 0.f, 0.f, 0.f);
            for (int j = jend + lane * 4; j < SQ; j += 128)
                *(float4*)(arow + j) = z;
        }
    }

    // ======================= PV (MMA) =======================
    // warps: ks2 = w>>1 (8 key slabs of 32), ng = w&1 (d half of 32).
    const int ks2 = w >> 1;
    const int ng  = w & 1;
    float pacc[4][4] = {};

    for (int jt = 0; jt < jend; jt += KT) {
        const int ktile = min(KT, jend - jt);
        __syncthreads();
        // V^T tile: vt[d][j], stride 260, contiguous loads from g_v[B,H,Dh,S]
        {
            const int nchunks = ktile >> 2;              // float4s per d-row
            for (int idx = tid; idx < DH * nchunks; idx += 512) {
                int d = idx / nchunks, jc = (idx % nchunks) * 4;
                float4 v = *(const float4*)&gv[(bh * DH + d) * SQ + jt + jc];
                *(float4*)&kq[d * 260 + jc] = v;
            }
        }
        __syncthreads();

        const int kb2 = ks2 * 32;
        if (kb2 < ktile) {
            #pragma unroll
            for (int kk2 = 0; kk2 < 4; kk2++) {
                const int kloc = kb2 + kk2 * 8;
                uint32_t af0 = f2tf32(sc[g * SCP       + jt + kloc + tig]);
                uint32_t af1 = f2tf32(sc[(g + 8) * SCP + jt + kloc + tig]);
                uint32_t af2 = f2tf32(sc[g * SCP       + jt + kloc + tig + 4]);
                uint32_t af3 = f2tf32(sc[(g + 8) * SCP + jt + kloc + tig + 4]);
                #pragma unroll
                for (int nt = 0; nt < 4; nt++) {
                    const int d = ng * 32 + nt * 8 + g;
                    uint32_t b0 = f2tf32(kq[d * 260 + kloc + tig]);
                    uint32_t b1 = f2tf32(kq[d * 260 + kloc + tig + 4]);
                    MMA_TF32(pacc[nt], af0, af1, af2, af3, b0, b1);
                }
            }
        }
    }

    // --- reduce partials across the 8 key-slab warps ---
    __syncthreads();
    float* red = kq;   // 7 * 16 * 64 floats = 7168
    if (ks2 > 0) {
        #pragma unroll
        for (int nt = 0; nt < 4; nt++) {
            const int col = ng * 32 + nt * 8 + 2 * tig;
            *(float2*)&red[((ks2 - 1) * 16 + g) * 64 + col]     = make_float2(pacc[nt][0], pacc[nt][1]);
            *(float2*)&red[((ks2 - 1) * 16 + g + 8) * 64 + col] = make_float2(pacc[nt][2], pacc[nt][3]);
        }
    }
    __syncthreads();
    if (ks2 == 0) {
        #pragma unroll
        for (int nt = 0; nt < 4; nt++) {
            const int col = ng * 32 + nt * 8 + 2 * tig;
            #pragma unroll
            for (int half = 0; half < 2; half++) {
                const int row = g + half * 8;
                float s0 = pacc[nt][half * 2 + 0];
                float s1 = pacc[nt][half * 2 + 1];
                #pragma unroll
                for (int p = 0; p < 7; p++) {
                    s0 += red[(p * 16 + row) * 64 + col];
                    s1 += red[(p * 16 + row) * 64 + col + 1];
                }
                const float inv = sinv[row];
                *(float2*)&out[(size_t)(b * SQ + i0 + row) * EE + h * DH + col] =
                    make_float2(s0 * inv, s1 * inv);
            }
        }
    }
}

// ---------------------------------------------------------------------------
extern "C" void kernel_launch(void* const* d_in, const int* in_sizes, int n_in,
                              void* d_out, int out_size)
{
    const float* x = (const float*)d_in[0];
    const float* W = (const float*)d_in[1];
    float* out = (float*)d_out;

    const long out_elems  = (long)BB * SQ * EE;
    const long attn_elems = (long)BB * HH * SQ * SQ;
    int write_attn = ((long)out_size >= out_elems + attn_elems) ? 1 : 0;
    float* attn = write_attn ? (out + out_elems) : nullptr;

    float *gq, *gk, *gv;
    cudaGetSymbolAddress((void**)&gq, g_q);
    cudaGetSymbolAddress((void**)&gk, g_k);
    cudaGetSymbolAddress((void**)&gv, g_v);

    // QKV projection (TF32 tensor cores) + scatter
    {
        int gemm_smem = 4 * ABUF * (int)sizeof(float);
        cudaFuncSetAttribute(qkv_gemm_tf32, cudaFuncAttributeMaxDynamicSharedMemorySize, gemm_smem);
        dim3 grid(GN / TN, GM / TM);
        qkv_gemm_tf32<<<grid, 256, gemm_smem>>>(x, W, gq, gk, gv);
    }

    // Fused attention (TF32 MMA)
    {
        int smem_bytes = (ROWS * SCP + 17408 + ROWS * 68 + 16) * (int)sizeof(float);
        cudaFuncSetAttribute(attn_kernel, cudaFuncAttributeMaxDynamicSharedMemorySize, smem_bytes);
        dim3 grid(SQ / ROWS, HH, BB);
        attn_kernel<<<grid, 512, smem_bytes>>>(gq, gk, gv, out, attn, write_attn);
    }
}